// round 14
// baseline (speedup 1.0000x reference)
#include <cuda_runtime.h>
#include <cuda_fp16.h>
#include <math.h>
#include <stdint.h>

// Problem constants: B=4, T=2048, C=768, H=12, D=64
#define Bv 4
#define Tv 2048
#define Cv 768
#define Hv 12
#define Dv 64
#define C3v (3 * Cv)     // 2304
#define Mv (Bv * Tv)     // 8192

// ---------------- device scratch (no allocation allowed) -------------------
__device__ __half g_x16[(size_t)Mv * Cv];
__device__ __half g_wA[(size_t)C3v * Cv];     // transposed [3C, C] fp16
__device__ __half g_wP[(size_t)Cv * Cv];      // transposed [C, C] fp16
__device__ __half g_q16[(size_t)Mv * Cv];     // [b,h,t,d], pre-scaled by 1/8
__device__ __half g_k16[(size_t)Mv * Cv];     // [b,h,t,d]
__device__ __half g_vt16[(size_t)Mv * Cv];    // [b,h,d,t]  (V transposed)
__device__ __half g_y16[(size_t)Mv * Cv];     // [b,t,h*d]

// ---------------------------------------------------------------------------
__device__ __forceinline__ void mma16816(float* c, const uint32_t* a,
                                         uint32_t b0, uint32_t b1) {
    asm volatile(
        "mma.sync.aligned.m16n8k16.row.col.f32.f16.f16.f32 "
        "{%0,%1,%2,%3}, {%4,%5,%6,%7}, {%8,%9}, {%0,%1,%2,%3};"
        : "+f"(c[0]), "+f"(c[1]), "+f"(c[2]), "+f"(c[3])
        : "r"(a[0]), "r"(a[1]), "r"(a[2]), "r"(a[3]), "r"(b0), "r"(b1));
}

__device__ __forceinline__ void ldsm4(uint32_t* r, uint32_t addr) {
    asm volatile("ldmatrix.sync.aligned.m8n8.x4.shared.b16 {%0,%1,%2,%3}, [%4];"
        : "=r"(r[0]), "=r"(r[1]), "=r"(r[2]), "=r"(r[3]) : "r"(addr));
}

__device__ __forceinline__ uint32_t smem_u32(const void* p) {
    uint32_t a;
    asm("{ .reg .u64 t; cvta.to.shared.u64 t, %1; cvt.u32.u64 %0, t; }" : "=r"(a) : "l"(p));
    return a;
}
#define CP16(dst, src) \
    asm volatile("cp.async.cg.shared.global [%0], [%1], 16;" :: "r"(dst), "l"(src))
#define CP_COMMIT() asm volatile("cp.async.commit_group;" ::: "memory")
#define CP_WAIT1()  asm volatile("cp.async.wait_group 1;" ::: "memory")

__device__ __forceinline__ uint32_t pack_h(float a, float b) {
    __half2 t;
    t.x = __float2half_rn(a);
    t.y = __float2half_rn(b);
    return *(uint32_t*)&t;
}

// ---------------------------------------------------------------------------
__global__ void cvt_kernel(const float* __restrict__ in,
                           __half* __restrict__ out16, int n) {
    int i = (blockIdx.x * 256 + threadIdx.x) * 4;
    if (i >= n) return;
    float4 v = *(const float4*)(in + i);
    *(uint32_t*)(out16 + i)     = pack_h(v.x, v.y);
    *(uint32_t*)(out16 + i + 2) = pack_h(v.z, v.w);
}

__global__ void transpose_cvt(const float* __restrict__ w,
                              __half* __restrict__ t_, int K, int N) {
    __shared__ float st[32][33];
    const int n0 = blockIdx.x * 32, k0 = blockIdx.y * 32;
    const int tx = threadIdx.x, ty = threadIdx.y;          // (32, 8)
    #pragma unroll
    for (int i = 0; i < 4; i++)
        st[ty + 8 * i][tx] = w[(size_t)(k0 + ty + 8 * i) * N + n0 + tx];
    __syncthreads();
    #pragma unroll
    for (int i = 0; i < 4; i++)
        t_[(size_t)(n0 + ty + 8 * i) * K + k0 + tx] =
            __float2half_rn(st[tx][ty + 8 * i]);
}

// ---------------------------------------------------------------------------
// fp16 GEMM: 128x64 tile, BK=64, 8 warps (4Mx2N), 3-stage cp.async
// (single barrier per chunk), ldmatrix, 2 CTAs/SM.
// MODE 0: C = A@B^T + bias -> fp32. MODE 1: QKV scatter epilogue.
// ---------------------------------------------------------------------------
#define GRS 72
#define GTA_BYTES 18432                // A tile: 128 * 72 * 2
#define GTB_BYTES 9216                 // B tile:  64 * 72 * 2
#define GB_OFF    (3 * GTA_BYTES)      // 55296
#define G_SMEM    (GB_OFF + 3 * GTB_BYTES)   // 82944

template <int MODE>
__global__ __launch_bounds__(256, 2)
void gemm_mma(const __half* __restrict__ Am, const __half* __restrict__ Bm,
              const float* __restrict__ bias, float* __restrict__ Cmat,
              __half* __restrict__ q16, __half* __restrict__ k16,
              __half* __restrict__ vt16, int N, int K) {
    extern __shared__ __align__(16) char gsm[];
    const uint32_t sb = smem_u32(gsm);

    const int tid = threadIdx.x;
    const int wid = tid >> 5, lane = tid & 31;
    const int g = lane >> 2, tig = lane & 3;
    const int bx = blockIdx.x, by = blockIdx.y;
    const int wm = (wid & 3) * 32;
    const int wn = (wid >> 2) * 32;

    const int aRow = lane & 15, aCol8 = (lane >> 4) * 8;
    const int bRow = ((lane >> 4) * 8) + (lane & 7);
    const int bCol8 = ((lane >> 3) & 1) * 8;

    float acc[2][4][4];
    #pragma unroll
    for (int mt = 0; mt < 2; mt++)
        #pragma unroll
        for (int nt = 0; nt < 4; nt++)
            #pragma unroll
            for (int j = 0; j < 4; j++) acc[mt][nt][j] = 0.f;

    const int nCh = K >> 6;                     // BK = 64

    auto load_chunk = [&](int c, int s) {
        const int k0 = c << 6;
        #pragma unroll
        for (int i = 0; i < 4; i++) {
            const int u = tid + i * 256;
            const int r = u >> 3, c8 = (u & 7) * 8;
            const size_t ga = (size_t)(by * 128 + r) * K + k0 + c8;
            CP16(sb + s * GTA_BYTES + (uint32_t)(r * 144 + c8 * 2), Am + ga);
        }
        #pragma unroll
        for (int i = 0; i < 2; i++) {
            const int u = tid + i * 256;
            const int r = u >> 3, c8 = (u & 7) * 8;
            const size_t gb = (size_t)(bx * 64 + r) * K + k0 + c8;
            CP16(sb + GB_OFF + s * GTB_BYTES + (uint32_t)(r * 144 + c8 * 2), Bm + gb);
        }
    };

    load_chunk(0, 0); CP_COMMIT();
    load_chunk(1, 1); CP_COMMIT();

    int s = 0;
    for (int c = 0; c < nCh; c++) {
        CP_WAIT1();                     // chunk c's group complete
        __syncthreads();                // all warps done with stage (c+2)%3's old data
        if (c + 2 < nCh) {
            const int s2 = (s + 2 >= 3) ? s - 1 : s + 2;
            load_chunk(c + 2, s2);
        }
        CP_COMMIT();                    // uniform group accounting (may be empty)

        const uint32_t abase = sb + s * GTA_BYTES;
        const uint32_t bbase = sb + GB_OFF + s * GTB_BYTES;
        #pragma unroll
        for (int ks = 0; ks < 4; ks++) {
            const int kc = ks * 16;
            uint32_t afr[2][4];
            #pragma unroll
            for (int mt = 0; mt < 2; mt++)
                ldsm4(afr[mt], abase +
                      ((wm + mt * 16 + aRow) * GRS + kc + aCol8) * 2);
            #pragma unroll
            for (int p = 0; p < 2; p++) {
                uint32_t bfr[4];
                ldsm4(bfr, bbase +
                      ((wn + p * 16 + bRow) * GRS + kc + bCol8) * 2);
                mma16816(acc[0][2 * p],     afr[0], bfr[0], bfr[1]);
                mma16816(acc[1][2 * p],     afr[1], bfr[0], bfr[1]);
                mma16816(acc[0][2 * p + 1], afr[0], bfr[2], bfr[3]);
                mma16816(acc[1][2 * p + 1], afr[1], bfr[2], bfr[3]);
            }
        }
        s = (s + 1 == 3) ? 0 : s + 1;
    }

    if (MODE == 0) {
        #pragma unroll
        for (int mt = 0; mt < 2; mt++) {
            #pragma unroll
            for (int nt = 0; nt < 4; nt++) {
                const int rg = by * 128 + wm + mt * 16 + g;
                const int cg = bx * 64 + wn + nt * 8 + tig * 2;
                const float bs0 = __ldg(bias + cg), bs1 = __ldg(bias + cg + 1);
                float2 v0, v1;
                v0.x = acc[mt][nt][0] + bs0;
                v0.y = acc[mt][nt][1] + bs1;
                v1.x = acc[mt][nt][2] + bs0;
                v1.y = acc[mt][nt][3] + bs1;
                *(float2*)(Cmat + (size_t)rg * N + cg)       = v0;
                *(float2*)(Cmat + (size_t)(rg + 8) * N + cg) = v1;
            }
        }
    } else {
        const int reg3 = bx / Hv;       // 0=Q, 1=K, 2=V
        const int h    = bx % Hv;
        #pragma unroll
        for (int mt = 0; mt < 2; mt++) {
            #pragma unroll
            for (int nt = 0; nt < 4; nt++) {
                const int rg = by * 128 + wm + mt * 16 + g;
                const int bb = rg >> 11, t = rg & 2047;
                const int d = wn + nt * 8 + tig * 2;
                const int cg = bx * 64 + d;
                const float bs0 = __ldg(bias + cg), bs1 = __ldg(bias + cg + 1);
                const float v0 = acc[mt][nt][0] + bs0;
                const float v1 = acc[mt][nt][1] + bs1;
                const float v2 = acc[mt][nt][2] + bs0;
                const float v3 = acc[mt][nt][3] + bs1;
                if (reg3 == 0) {
                    const size_t o = ((size_t)(bb * Hv + h) * Tv + t) * Dv + d;
                    *(uint32_t*)(q16 + o)           = pack_h(v0 * 0.125f, v1 * 0.125f);
                    *(uint32_t*)(q16 + o + 8 * Dv)  = pack_h(v2 * 0.125f, v3 * 0.125f);
                } else if (reg3 == 1) {
                    const size_t o = ((size_t)(bb * Hv + h) * Tv + t) * Dv + d;
                    *(uint32_t*)(k16 + o)           = pack_h(v0, v1);
                    *(uint32_t*)(k16 + o + 8 * Dv)  = pack_h(v2, v3);
                } else {
                    const size_t o = ((size_t)(bb * Hv + h) * Dv + d) * Tv + t;
                    vt16[o]          = __float2half_rn(v0);
                    vt16[o + Tv]     = __float2half_rn(v1);
                    vt16[o + 8]      = __float2half_rn(v2);
                    vt16[o + Tv + 8] = __float2half_rn(v3);
                }
            }
        }
    }
}

// ---------------------------------------------------------------------------
// fp16 causal flash attention, 3-stage cp.async (single barrier per block),
// causal-masked-tile MMA skip.
// ---------------------------------------------------------------------------
#define AKS 72               // smem row stride (fp16)
#define AT_BYTES 9216        // 64 * 72 * 2
#define A_OFF_K 0                      // 3 stages
#define A_OFF_V (3 * AT_BYTES)         // 3 stages
#define A_SMEM  (6 * AT_BYTES)         // 55296

__global__ __launch_bounds__(256, 2)
void attn_mma(const __half* __restrict__ q16, const __half* __restrict__ k16,
              const __half* __restrict__ vt16, __half* __restrict__ y16) {
    extern __shared__ char sm[];
    const uint32_t sbase = smem_u32(sm);

    const int qt = (gridDim.x - 1) - blockIdx.x;   // heavy blocks first
    const int h  = blockIdx.y;
    const int b  = blockIdx.z;
    const int tid = threadIdx.x;
    const int wid = tid >> 5, lane = tid & 31;
    const int g = lane >> 2, tig = lane & 3;

    const int bRow = ((lane >> 4) * 8) + (lane & 7);
    const int bCol8 = ((lane >> 3) & 1) * 8;

    const int qr0 = qt * 128;
    const int row0 = qr0 + wid * 16 + g;
    const int warpRowMax = qr0 + wid * 16 + 15;
    const size_t qb  = (size_t)(b * Hv + h) * Tv * Dv;
    const size_t vtb = (size_t)(b * Hv + h) * Dv * Tv;

    auto load_kv = [&](int kvb, int s) {
        const int kv0 = kvb * 64;
        #pragma unroll
        for (int i = 0; i < 2; i++) {
            const int u = tid + i * 256;
            const int r = u >> 3, c8 = (u & 7) * 8;
            CP16(sbase + A_OFF_K + s * AT_BYTES + (uint32_t)(r * 144 + c8 * 2),
                 k16 + qb + (size_t)(kv0 + r) * Dv + c8);
            CP16(sbase + A_OFF_V + s * AT_BYTES + (uint32_t)(r * 144 + c8 * 2),
                 vt16 + vtb + (size_t)r * Tv + kv0 + c8);
        }
    };

    uint32_t qh[4][4];
    #pragma unroll
    for (int ks = 0; ks < 4; ks++) {
        const int kc = ks * 16 + tig * 2;
        #pragma unroll
        for (int j = 0; j < 4; j++) {
            const int rr = (j & 1) ? row0 + 8 : row0;
            const int cc = kc + ((j >> 1) ? 8 : 0);
            qh[ks][j] = *(const uint32_t*)(q16 + qb + (size_t)rr * Dv + cc);
        }
    }

    float acc_o[8][4];
    #pragma unroll
    for (int nt = 0; nt < 8; nt++)
        #pragma unroll
        for (int j = 0; j < 4; j++) acc_o[nt][j] = 0.f;
    float m0 = -INFINITY, m1 = -INFINITY, l0 = 0.f, l1 = 0.f;

    const int nkv = (qr0 >> 6) + 2;
    load_kv(0, 0); CP_COMMIT();
    load_kv(1, 1); CP_COMMIT();

    int s = 0;
    for (int kvb = 0; kvb < nkv; kvb++) {
        const int kv0 = kvb * 64;
        CP_WAIT1();
        __syncthreads();
        if (kvb + 2 < nkv) {
            const int s2 = (s + 2 >= 3) ? s - 1 : s + 2;
            load_kv(kvb + 2, s2);
        }
        CP_COMMIT();

        if (kv0 <= warpRowMax) {
            const uint32_t kbase = sbase + A_OFF_K + s * AT_BYTES;
            const uint32_t vbase = sbase + A_OFF_V + s * AT_BYTES;
            float s_[8][4];
            #pragma unroll
            for (int nt = 0; nt < 8; nt++)
                #pragma unroll
                for (int j = 0; j < 4; j++) s_[nt][j] = 0.f;

            // S = Q K^T (skip fully-masked 16-col tiles; warp-uniform predicate)
            #pragma unroll
            for (int ks = 0; ks < 4; ks++) {
                const int kc = ks * 16;
                #pragma unroll
                for (int p = 0; p < 4; p++) {
                    if (kv0 + p * 16 <= warpRowMax) {
                        uint32_t bfr[4];
                        ldsm4(bfr, kbase + ((p * 16 + bRow) * AKS + kc + bCol8) * 2);
                        mma16816(s_[2 * p],     qh[ks], bfr[0], bfr[1]);
                        mma16816(s_[2 * p + 1], qh[ks], bfr[2], bfr[3]);
                    }
                }
            }

            float rmax0 = -INFINITY, rmax1 = -INFINITY;
            #pragma unroll
            for (int nt = 0; nt < 8; nt++) {
                const int colb = kv0 + nt * 8 + tig * 2;
                #pragma unroll
                for (int j = 0; j < 2; j++) {
                    if (colb + j > row0)     s_[nt][j]     = -INFINITY;
                    if (colb + j > row0 + 8) s_[nt][2 + j] = -INFINITY;
                    rmax0 = fmaxf(rmax0, s_[nt][j]);
                    rmax1 = fmaxf(rmax1, s_[nt][2 + j]);
                }
            }
            rmax0 = fmaxf(rmax0, __shfl_xor_sync(0xffffffff, rmax0, 1));
            rmax0 = fmaxf(rmax0, __shfl_xor_sync(0xffffffff, rmax0, 2));
            rmax1 = fmaxf(rmax1, __shfl_xor_sync(0xffffffff, rmax1, 1));
            rmax1 = fmaxf(rmax1, __shfl_xor_sync(0xffffffff, rmax1, 2));

            const float mn0 = fmaxf(m0, rmax0);
            const float mn1 = fmaxf(m1, rmax1);
            const float cr0 = __expf(m0 - mn0);
            const float cr1 = __expf(m1 - mn1);
            l0 *= cr0; l1 *= cr1;
            #pragma unroll
            for (int nt = 0; nt < 8; nt++) {
                acc_o[nt][0] *= cr0; acc_o[nt][1] *= cr0;
                acc_o[nt][2] *= cr1; acc_o[nt][3] *= cr1;
            }
            m0 = mn0; m1 = mn1;

            uint32_t ph[4][4];
            float rs0 = 0.f, rs1 = 0.f;
            #pragma unroll
            for (int kt = 0; kt < 4; kt++) {
                float p00, p01, p10, p11;
                p00 = __expf(s_[2 * kt][0] - mn0);
                p01 = __expf(s_[2 * kt][1] - mn0);
                p10 = __expf(s_[2 * kt][2] - mn1);
                p11 = __expf(s_[2 * kt][3] - mn1);
                rs0 += p00 + p01; rs1 += p10 + p11;
                ph[kt][0] = pack_h(p00, p01);
                ph[kt][1] = pack_h(p10, p11);
                p00 = __expf(s_[2 * kt + 1][0] - mn0);
                p01 = __expf(s_[2 * kt + 1][1] - mn0);
                p10 = __expf(s_[2 * kt + 1][2] - mn1);
                p11 = __expf(s_[2 * kt + 1][3] - mn1);
                rs0 += p00 + p01; rs1 += p10 + p11;
                ph[kt][2] = pack_h(p00, p01);
                ph[kt][3] = pack_h(p10, p11);
            }
            rs0 += __shfl_xor_sync(0xffffffff, rs0, 1);
            rs0 += __shfl_xor_sync(0xffffffff, rs0, 2);
            rs1 += __shfl_xor_sync(0xffffffff, rs1, 1);
            rs1 += __shfl_xor_sync(0xffffffff, rs1, 2);
            l0 += rs0; l1 += rs1;

            // O += P V (skip kt tiles whose weights are exactly zero)
            #pragma unroll
            for (int kt = 0; kt < 4; kt++) {
                if (kv0 + kt * 16 <= warpRowMax) {
                    const int kc = kt * 16;
                    #pragma unroll
                    for (int p = 0; p < 4; p++) {
                        uint32_t bfr[4];
                        ldsm4(bfr, vbase + ((p * 16 + bRow) * AKS + kc + bCol8) * 2);
                        mma16816(acc_o[2 * p],     ph[kt], bfr[0], bfr[1]);
                        mma16816(acc_o[2 * p + 1], ph[kt], bfr[2], bfr[3]);
                    }
                }
            }
        }
        s = (s + 1 == 3) ? 0 : s + 1;
    }

    const float i0 = 1.f / l0, i1 = 1.f / l1;
    #pragma unroll
    for (int nt = 0; nt < 8; nt++) {
        const int d = nt * 8 + tig * 2;
        const size_t o0 = ((size_t)b * Tv + row0) * Cv + h * Dv + d;
        const size_t o1 = o0 + (size_t)8 * Cv;
        *(uint32_t*)(y16 + o0) = pack_h(acc_o[nt][0] * i0, acc_o[nt][1] * i0);
        *(uint32_t*)(y16 + o1) = pack_h(acc_o[nt][2] * i1, acc_o[nt][3] * i1);
    }
}

// ---------------------------------------------------------------------------
extern "C" void kernel_launch(void* const* d_in, const int* in_sizes, int n_in,
                              void* d_out, int out_size) {
    const float* x      = (const float*)d_in[0];
    const float* w_attn = (const float*)d_in[1];
    const float* b_attn = (const float*)d_in[2];
    const float* w_proj = (const float*)d_in[3];
    const float* b_proj = (const float*)d_in[4];
    float* out = (float*)d_out;

    __half *x16, *wA, *wP, *q16, *k16, *vt16, *y16;
    cudaGetSymbolAddress((void**)&x16, g_x16);
    cudaGetSymbolAddress((void**)&wA, g_wA);
    cudaGetSymbolAddress((void**)&wP, g_wP);
    cudaGetSymbolAddress((void**)&q16, g_q16);
    cudaGetSymbolAddress((void**)&k16, g_k16);
    cudaGetSymbolAddress((void**)&vt16, g_vt16);
    cudaGetSymbolAddress((void**)&y16, g_y16);

    cudaFuncSetAttribute(gemm_mma<0>, cudaFuncAttributeMaxDynamicSharedMemorySize, G_SMEM);
    cudaFuncSetAttribute(gemm_mma<1>, cudaFuncAttributeMaxDynamicSharedMemorySize, G_SMEM);
    cudaFuncSetAttribute(attn_mma, cudaFuncAttributeMaxDynamicSharedMemorySize, A_SMEM);

    const int nx = Mv * Cv;
    cvt_kernel<<<(nx / 4 + 255) / 256, 256>>>(x, x16, nx);
    transpose_cvt<<<dim3(C3v / 32, Cv / 32), dim3(32, 8)>>>(w_attn, wA, Cv, C3v);
    transpose_cvt<<<dim3(Cv / 32, Cv / 32), dim3(32, 8)>>>(w_proj, wP, Cv, Cv);

    // 1) QKV GEMM with fused scatter epilogue -> q16 (scaled), k16, vt16
    gemm_mma<1><<<dim3(C3v / 64, Mv / 128), 256, G_SMEM>>>(
        x16, wA, b_attn, nullptr, q16, k16, vt16, C3v, Cv);
    // 2) causal flash attention (all-fp16 operands, 3-stage pipeline)
    attn_mma<<<dim3(Tv / 128, Hv, Bv), 256, A_SMEM>>>(q16, k16, vt16, y16);
    // 3) out = y @ w_proj + b_proj (fp32 out)
    gemm_mma<0><<<dim3(Cv / 64, Mv / 128), 256, G_SMEM>>>(
        y16, wP, b_proj, out, nullptr, nullptr, nullptr, Cv, Cv);
}

// round 15
// speedup vs baseline: 1.0252x; 1.0252x over previous
#include <cuda_runtime.h>
#include <cuda_fp16.h>
#include <math.h>
#include <stdint.h>

// Problem constants: B=4, T=2048, C=768, H=12, D=64
#define Bv 4
#define Tv 2048
#define Cv 768
#define Hv 12
#define Dv 64
#define C3v (3 * Cv)     // 2304
#define Mv (Bv * Tv)     // 8192

// ---------------- device scratch (no allocation allowed) -------------------
__device__ __half g_x16[(size_t)Mv * Cv];
__device__ __half g_wA[(size_t)C3v * Cv];     // transposed [3C, C] fp16
__device__ __half g_wP[(size_t)Cv * Cv];      // transposed [C, C] fp16
__device__ __half g_q16[(size_t)Mv * Cv];     // [b,h,t,d], pre-scaled by 1/8
__device__ __half g_k16[(size_t)Mv * Cv];     // [b,h,t,d]
__device__ __half g_vt16[(size_t)Mv * Cv];    // [b,h,d,t]  (V transposed)
__device__ __half g_y16[(size_t)Mv * Cv];     // [b,t,h*d]

// ---------------------------------------------------------------------------
__device__ __forceinline__ void mma16816(float* c, const uint32_t* a,
                                         uint32_t b0, uint32_t b1) {
    asm volatile(
        "mma.sync.aligned.m16n8k16.row.col.f32.f16.f16.f32 "
        "{%0,%1,%2,%3}, {%4,%5,%6,%7}, {%8,%9}, {%0,%1,%2,%3};"
        : "+f"(c[0]), "+f"(c[1]), "+f"(c[2]), "+f"(c[3])
        : "r"(a[0]), "r"(a[1]), "r"(a[2]), "r"(a[3]), "r"(b0), "r"(b1));
}

__device__ __forceinline__ void ldsm4(uint32_t* r, uint32_t addr) {
    asm volatile("ldmatrix.sync.aligned.m8n8.x4.shared.b16 {%0,%1,%2,%3}, [%4];"
        : "=r"(r[0]), "=r"(r[1]), "=r"(r[2]), "=r"(r[3]) : "r"(addr));
}

__device__ __forceinline__ uint32_t smem_u32(const void* p) {
    uint32_t a;
    asm("{ .reg .u64 t; cvta.to.shared.u64 t, %1; cvt.u32.u64 %0, t; }" : "=r"(a) : "l"(p));
    return a;
}
#define CP16(dst, src) \
    asm volatile("cp.async.cg.shared.global [%0], [%1], 16;" :: "r"(dst), "l"(src))
#define CP_COMMIT() asm volatile("cp.async.commit_group;" ::: "memory")
#define CP_WAIT1()  asm volatile("cp.async.wait_group 1;" ::: "memory")

__device__ __forceinline__ uint32_t pack_h(float a, float b) {
    __half2 t;
    t.x = __float2half_rn(a);
    t.y = __float2half_rn(b);
    return *(uint32_t*)&t;
}

// ---------------------------------------------------------------------------
// Fused prep: one launch does x->fp16 convert + both weight transposes.
//   blocks [0, PX)            : convert x (4 elems/thread)
//   blocks [PX, PX+PWA)       : transpose+cvt w_attn (32x32 tile per block)
//   blocks [PX+PWA, ...)      : transpose+cvt w_proj
// ---------------------------------------------------------------------------
#define PX   (Mv * Cv / 1024)              // 6144
#define PWA  ((C3v / 32) * (Cv / 32))      // 1728
#define PWP  ((Cv / 32) * (Cv / 32))       // 576
#define PREP_BLOCKS (PX + PWA + PWP)       // 8448

__global__ void prep_kernel(const float* __restrict__ x, __half* __restrict__ x16,
                            const float* __restrict__ wA, __half* __restrict__ wA16,
                            const float* __restrict__ wP, __half* __restrict__ wP16) {
    __shared__ float st[32][33];
    int blk = blockIdx.x;
    if (blk < PX) {
        const int i = (blk * 256 + threadIdx.x) * 4;
        float4 v = *(const float4*)(x + i);
        *(uint32_t*)(x16 + i)     = pack_h(v.x, v.y);
        *(uint32_t*)(x16 + i + 2) = pack_h(v.z, v.w);
        return;
    }
    blk -= PX;
    const float* w;
    __half* t_;
    int N, nbx;
    if (blk < PWA) { w = wA; t_ = wA16; N = C3v; nbx = C3v / 32; }
    else           { blk -= PWA; w = wP; t_ = wP16; N = Cv; nbx = Cv / 32; }
    const int K = Cv;
    const int n0 = (blk % nbx) * 32, k0 = (blk / nbx) * 32;
    const int tx = threadIdx.x & 31, ty = threadIdx.x >> 5;   // (32, 8)
    #pragma unroll
    for (int i = 0; i < 4; i++)
        st[ty + 8 * i][tx] = w[(size_t)(k0 + ty + 8 * i) * N + n0 + tx];
    __syncthreads();
    #pragma unroll
    for (int i = 0; i < 4; i++)
        t_[(size_t)(n0 + ty + 8 * i) * K + k0 + tx] =
            __float2half_rn(st[tx][ty + 8 * i]);
}

// ---------------------------------------------------------------------------
// fp16 GEMM: 128x64 tile, BK=64, 8 warps (4Mx2N), 3-stage cp.async
// (single barrier per chunk), ldmatrix, 2 CTAs/SM.
// MODE 0: C = A@B^T + bias -> fp32. MODE 1: QKV scatter epilogue.
// ---------------------------------------------------------------------------
#define GRS 72
#define GTA_BYTES 18432                // A tile: 128 * 72 * 2
#define GTB_BYTES 9216                 // B tile:  64 * 72 * 2
#define GB_OFF    (3 * GTA_BYTES)      // 55296
#define G_SMEM    (GB_OFF + 3 * GTB_BYTES)   // 82944

template <int MODE>
__global__ __launch_bounds__(256, 2)
void gemm_mma(const __half* __restrict__ Am, const __half* __restrict__ Bm,
              const float* __restrict__ bias, float* __restrict__ Cmat,
              __half* __restrict__ q16, __half* __restrict__ k16,
              __half* __restrict__ vt16, int N, int K) {
    extern __shared__ __align__(16) char gsm[];
    const uint32_t sb = smem_u32(gsm);

    const int tid = threadIdx.x;
    const int wid = tid >> 5, lane = tid & 31;
    const int g = lane >> 2, tig = lane & 3;
    const int bx = blockIdx.x, by = blockIdx.y;
    const int wm = (wid & 3) * 32;
    const int wn = (wid >> 2) * 32;

    const int aRow = lane & 15, aCol8 = (lane >> 4) * 8;
    const int bRow = ((lane >> 4) * 8) + (lane & 7);
    const int bCol8 = ((lane >> 3) & 1) * 8;

    float acc[2][4][4];
    #pragma unroll
    for (int mt = 0; mt < 2; mt++)
        #pragma unroll
        for (int nt = 0; nt < 4; nt++)
            #pragma unroll
            for (int j = 0; j < 4; j++) acc[mt][nt][j] = 0.f;

    const int nCh = K >> 6;                     // BK = 64

    auto load_chunk = [&](int c, int s) {
        const int k0 = c << 6;
        #pragma unroll
        for (int i = 0; i < 4; i++) {
            const int u = tid + i * 256;
            const int r = u >> 3, c8 = (u & 7) * 8;
            const size_t ga = (size_t)(by * 128 + r) * K + k0 + c8;
            CP16(sb + s * GTA_BYTES + (uint32_t)(r * 144 + c8 * 2), Am + ga);
        }
        #pragma unroll
        for (int i = 0; i < 2; i++) {
            const int u = tid + i * 256;
            const int r = u >> 3, c8 = (u & 7) * 8;
            const size_t gb = (size_t)(bx * 64 + r) * K + k0 + c8;
            CP16(sb + GB_OFF + s * GTB_BYTES + (uint32_t)(r * 144 + c8 * 2), Bm + gb);
        }
    };

    load_chunk(0, 0); CP_COMMIT();
    load_chunk(1, 1); CP_COMMIT();

    int s = 0;
    for (int c = 0; c < nCh; c++) {
        CP_WAIT1();
        __syncthreads();
        if (c + 2 < nCh) {
            const int s2 = (s + 2 >= 3) ? s - 1 : s + 2;
            load_chunk(c + 2, s2);
        }
        CP_COMMIT();

        const uint32_t abase = sb + s * GTA_BYTES;
        const uint32_t bbase = sb + GB_OFF + s * GTB_BYTES;
        #pragma unroll
        for (int ks = 0; ks < 4; ks++) {
            const int kc = ks * 16;
            uint32_t afr[2][4];
            #pragma unroll
            for (int mt = 0; mt < 2; mt++)
                ldsm4(afr[mt], abase +
                      ((wm + mt * 16 + aRow) * GRS + kc + aCol8) * 2);
            #pragma unroll
            for (int p = 0; p < 2; p++) {
                uint32_t bfr[4];
                ldsm4(bfr, bbase +
                      ((wn + p * 16 + bRow) * GRS + kc + bCol8) * 2);
                mma16816(acc[0][2 * p],     afr[0], bfr[0], bfr[1]);
                mma16816(acc[1][2 * p],     afr[1], bfr[0], bfr[1]);
                mma16816(acc[0][2 * p + 1], afr[0], bfr[2], bfr[3]);
                mma16816(acc[1][2 * p + 1], afr[1], bfr[2], bfr[3]);
            }
        }
        s = (s + 1 == 3) ? 0 : s + 1;
    }

    if (MODE == 0) {
        #pragma unroll
        for (int mt = 0; mt < 2; mt++) {
            #pragma unroll
            for (int nt = 0; nt < 4; nt++) {
                const int rg = by * 128 + wm + mt * 16 + g;
                const int cg = bx * 64 + wn + nt * 8 + tig * 2;
                const float bs0 = __ldg(bias + cg), bs1 = __ldg(bias + cg + 1);
                float2 v0, v1;
                v0.x = acc[mt][nt][0] + bs0;
                v0.y = acc[mt][nt][1] + bs1;
                v1.x = acc[mt][nt][2] + bs0;
                v1.y = acc[mt][nt][3] + bs1;
                *(float2*)(Cmat + (size_t)rg * N + cg)       = v0;
                *(float2*)(Cmat + (size_t)(rg + 8) * N + cg) = v1;
            }
        }
    } else {
        const int reg3 = bx / Hv;       // 0=Q, 1=K, 2=V
        const int h    = bx % Hv;
        #pragma unroll
        for (int mt = 0; mt < 2; mt++) {
            #pragma unroll
            for (int nt = 0; nt < 4; nt++) {
                const int rg = by * 128 + wm + mt * 16 + g;
                const int bb = rg >> 11, t = rg & 2047;
                const int d = wn + nt * 8 + tig * 2;
                const int cg = bx * 64 + d;
                const float bs0 = __ldg(bias + cg), bs1 = __ldg(bias + cg + 1);
                const float v0 = acc[mt][nt][0] + bs0;
                const float v1 = acc[mt][nt][1] + bs1;
                const float v2 = acc[mt][nt][2] + bs0;
                const float v3 = acc[mt][nt][3] + bs1;
                if (reg3 == 0) {
                    const size_t o = ((size_t)(bb * Hv + h) * Tv + t) * Dv + d;
                    *(uint32_t*)(q16 + o)           = pack_h(v0 * 0.125f, v1 * 0.125f);
                    *(uint32_t*)(q16 + o + 8 * Dv)  = pack_h(v2 * 0.125f, v3 * 0.125f);
                } else if (reg3 == 1) {
                    const size_t o = ((size_t)(bb * Hv + h) * Tv + t) * Dv + d;
                    *(uint32_t*)(k16 + o)           = pack_h(v0, v1);
                    *(uint32_t*)(k16 + o + 8 * Dv)  = pack_h(v2, v3);
                } else {
                    const size_t o = ((size_t)(bb * Hv + h) * Dv + d) * Tv + t;
                    vt16[o]          = __float2half_rn(v0);
                    vt16[o + Tv]     = __float2half_rn(v1);
                    vt16[o + 8]      = __float2half_rn(v2);
                    vt16[o + Tv + 8] = __float2half_rn(v3);
                }
            }
        }
    }
}

// ---------------------------------------------------------------------------
// fp16 causal flash attention, 3-stage cp.async (single barrier per block),
// causal-masked-tile MMA skip.
// ---------------------------------------------------------------------------
#define AKS 72               // smem row stride (fp16)
#define AT_BYTES 9216        // 64 * 72 * 2
#define A_OFF_K 0                      // 3 stages
#define A_OFF_V (3 * AT_BYTES)         // 3 stages
#define A_SMEM  (6 * AT_BYTES)         // 55296

__global__ __launch_bounds__(256, 2)
void attn_mma(const __half* __restrict__ q16, const __half* __restrict__ k16,
              const __half* __restrict__ vt16, __half* __restrict__ y16) {
    extern __shared__ char sm[];
    const uint32_t sbase = smem_u32(sm);

    const int qt = (gridDim.x - 1) - blockIdx.x;   // heavy blocks first
    const int h  = blockIdx.y;
    const int b  = blockIdx.z;
    const int tid = threadIdx.x;
    const int wid = tid >> 5, lane = tid & 31;
    const int g = lane >> 2, tig = lane & 3;

    const int bRow = ((lane >> 4) * 8) + (lane & 7);
    const int bCol8 = ((lane >> 3) & 1) * 8;

    const int qr0 = qt * 128;
    const int row0 = qr0 + wid * 16 + g;
    const int warpRowMax = qr0 + wid * 16 + 15;
    const size_t qb  = (size_t)(b * Hv + h) * Tv * Dv;
    const size_t vtb = (size_t)(b * Hv + h) * Dv * Tv;

    auto load_kv = [&](int kvb, int s) {
        const int kv0 = kvb * 64;
        #pragma unroll
        for (int i = 0; i < 2; i++) {
            const int u = tid + i * 256;
            const int r = u >> 3, c8 = (u & 7) * 8;
            CP16(sbase + A_OFF_K + s * AT_BYTES + (uint32_t)(r * 144 + c8 * 2),
                 k16 + qb + (size_t)(kv0 + r) * Dv + c8);
            CP16(sbase + A_OFF_V + s * AT_BYTES + (uint32_t)(r * 144 + c8 * 2),
                 vt16 + vtb + (size_t)r * Tv + kv0 + c8);
        }
    };

    uint32_t qh[4][4];
    #pragma unroll
    for (int ks = 0; ks < 4; ks++) {
        const int kc = ks * 16 + tig * 2;
        #pragma unroll
        for (int j = 0; j < 4; j++) {
            const int rr = (j & 1) ? row0 + 8 : row0;
            const int cc = kc + ((j >> 1) ? 8 : 0);
            qh[ks][j] = *(const uint32_t*)(q16 + qb + (size_t)rr * Dv + cc);
        }
    }

    float acc_o[8][4];
    #pragma unroll
    for (int nt = 0; nt < 8; nt++)
        #pragma unroll
        for (int j = 0; j < 4; j++) acc_o[nt][j] = 0.f;
    float m0 = -INFINITY, m1 = -INFINITY, l0 = 0.f, l1 = 0.f;

    const int nkv = (qr0 >> 6) + 2;
    load_kv(0, 0); CP_COMMIT();
    load_kv(1, 1); CP_COMMIT();

    int s = 0;
    for (int kvb = 0; kvb < nkv; kvb++) {
        const int kv0 = kvb * 64;
        CP_WAIT1();
        __syncthreads();
        if (kvb + 2 < nkv) {
            const int s2 = (s + 2 >= 3) ? s - 1 : s + 2;
            load_kv(kvb + 2, s2);
        }
        CP_COMMIT();

        if (kv0 <= warpRowMax) {
            const uint32_t kbase = sbase + A_OFF_K + s * AT_BYTES;
            const uint32_t vbase = sbase + A_OFF_V + s * AT_BYTES;
            float s_[8][4];
            #pragma unroll
            for (int nt = 0; nt < 8; nt++)
                #pragma unroll
                for (int j = 0; j < 4; j++) s_[nt][j] = 0.f;

            #pragma unroll
            for (int ks = 0; ks < 4; ks++) {
                const int kc = ks * 16;
                #pragma unroll
                for (int p = 0; p < 4; p++) {
                    if (kv0 + p * 16 <= warpRowMax) {
                        uint32_t bfr[4];
                        ldsm4(bfr, kbase + ((p * 16 + bRow) * AKS + kc + bCol8) * 2);
                        mma16816(s_[2 * p],     qh[ks], bfr[0], bfr[1]);
                        mma16816(s_[2 * p + 1], qh[ks], bfr[2], bfr[3]);
                    }
                }
            }

            float rmax0 = -INFINITY, rmax1 = -INFINITY;
            #pragma unroll
            for (int nt = 0; nt < 8; nt++) {
                const int colb = kv0 + nt * 8 + tig * 2;
                #pragma unroll
                for (int j = 0; j < 2; j++) {
                    if (colb + j > row0)     s_[nt][j]     = -INFINITY;
                    if (colb + j > row0 + 8) s_[nt][2 + j] = -INFINITY;
                    rmax0 = fmaxf(rmax0, s_[nt][j]);
                    rmax1 = fmaxf(rmax1, s_[nt][2 + j]);
                }
            }
            rmax0 = fmaxf(rmax0, __shfl_xor_sync(0xffffffff, rmax0, 1));
            rmax0 = fmaxf(rmax0, __shfl_xor_sync(0xffffffff, rmax0, 2));
            rmax1 = fmaxf(rmax1, __shfl_xor_sync(0xffffffff, rmax1, 1));
            rmax1 = fmaxf(rmax1, __shfl_xor_sync(0xffffffff, rmax1, 2));

            const float mn0 = fmaxf(m0, rmax0);
            const float mn1 = fmaxf(m1, rmax1);
            const float cr0 = __expf(m0 - mn0);
            const float cr1 = __expf(m1 - mn1);
            l0 *= cr0; l1 *= cr1;
            #pragma unroll
            for (int nt = 0; nt < 8; nt++) {
                acc_o[nt][0] *= cr0; acc_o[nt][1] *= cr0;
                acc_o[nt][2] *= cr1; acc_o[nt][3] *= cr1;
            }
            m0 = mn0; m1 = mn1;

            uint32_t ph[4][4];
            float rs0 = 0.f, rs1 = 0.f;
            #pragma unroll
            for (int kt = 0; kt < 4; kt++) {
                float p00, p01, p10, p11;
                p00 = __expf(s_[2 * kt][0] - mn0);
                p01 = __expf(s_[2 * kt][1] - mn0);
                p10 = __expf(s_[2 * kt][2] - mn1);
                p11 = __expf(s_[2 * kt][3] - mn1);
                rs0 += p00 + p01; rs1 += p10 + p11;
                ph[kt][0] = pack_h(p00, p01);
                ph[kt][1] = pack_h(p10, p11);
                p00 = __expf(s_[2 * kt + 1][0] - mn0);
                p01 = __expf(s_[2 * kt + 1][1] - mn0);
                p10 = __expf(s_[2 * kt + 1][2] - mn1);
                p11 = __expf(s_[2 * kt + 1][3] - mn1);
                rs0 += p00 + p01; rs1 += p10 + p11;
                ph[kt][2] = pack_h(p00, p01);
                ph[kt][3] = pack_h(p10, p11);
            }
            rs0 += __shfl_xor_sync(0xffffffff, rs0, 1);
            rs0 += __shfl_xor_sync(0xffffffff, rs0, 2);
            rs1 += __shfl_xor_sync(0xffffffff, rs1, 1);
            rs1 += __shfl_xor_sync(0xffffffff, rs1, 2);
            l0 += rs0; l1 += rs1;

            #pragma unroll
            for (int kt = 0; kt < 4; kt++) {
                if (kv0 + kt * 16 <= warpRowMax) {
                    const int kc = kt * 16;
                    #pragma unroll
                    for (int p = 0; p < 4; p++) {
                        uint32_t bfr[4];
                        ldsm4(bfr, vbase + ((p * 16 + bRow) * AKS + kc + bCol8) * 2);
                        mma16816(acc_o[2 * p],     ph[kt], bfr[0], bfr[1]);
                        mma16816(acc_o[2 * p + 1], ph[kt], bfr[2], bfr[3]);
                    }
                }
            }
        }
        s = (s + 1 == 3) ? 0 : s + 1;
    }

    const float i0 = 1.f / l0, i1 = 1.f / l1;
    #pragma unroll
    for (int nt = 0; nt < 8; nt++) {
        const int d = nt * 8 + tig * 2;
        const size_t o0 = ((size_t)b * Tv + row0) * Cv + h * Dv + d;
        const size_t o1 = o0 + (size_t)8 * Cv;
        *(uint32_t*)(y16 + o0) = pack_h(acc_o[nt][0] * i0, acc_o[nt][1] * i0);
        *(uint32_t*)(y16 + o1) = pack_h(acc_o[nt][2] * i1, acc_o[nt][3] * i1);
    }
}

// ---------------------------------------------------------------------------
extern "C" void kernel_launch(void* const* d_in, const int* in_sizes, int n_in,
                              void* d_out, int out_size) {
    const float* x      = (const float*)d_in[0];
    const float* w_attn = (const float*)d_in[1];
    const float* b_attn = (const float*)d_in[2];
    const float* w_proj = (const float*)d_in[3];
    const float* b_proj = (const float*)d_in[4];
    float* out = (float*)d_out;

    __half *x16, *wA, *wP, *q16, *k16, *vt16, *y16;
    cudaGetSymbolAddress((void**)&x16, g_x16);
    cudaGetSymbolAddress((void**)&wA, g_wA);
    cudaGetSymbolAddress((void**)&wP, g_wP);
    cudaGetSymbolAddress((void**)&q16, g_q16);
    cudaGetSymbolAddress((void**)&k16, g_k16);
    cudaGetSymbolAddress((void**)&vt16, g_vt16);
    cudaGetSymbolAddress((void**)&y16, g_y16);

    cudaFuncSetAttribute(gemm_mma<0>, cudaFuncAttributeMaxDynamicSharedMemorySize, G_SMEM);
    cudaFuncSetAttribute(gemm_mma<1>, cudaFuncAttributeMaxDynamicSharedMemorySize, G_SMEM);
    cudaFuncSetAttribute(attn_mma, cudaFuncAttributeMaxDynamicSharedMemorySize, A_SMEM);

    // 0) fused prep: x->fp16 + both weight transposes (single launch)
    prep_kernel<<<PREP_BLOCKS, 256>>>(x, x16, w_attn, wA, w_proj, wP);

    // 1) QKV GEMM with fused scatter epilogue -> q16 (scaled), k16, vt16
    gemm_mma<1><<<dim3(C3v / 64, Mv / 128), 256, G_SMEM>>>(
        x16, wA, b_attn, nullptr, q16, k16, vt16, C3v, Cv);
    // 2) causal flash attention (all-fp16 operands, 3-stage pipeline)
    attn_mma<<<dim3(Tv / 128, Hv, Bv), 256, A_SMEM>>>(q16, k16, vt16, y16);
    // 3) out = y @ w_proj + b_proj (fp32 out)
    gemm_mma<0><<<dim3(Cv / 64, Mv / 128), 256, G_SMEM>>>(
        y16, wP, b_proj, out, nullptr, nullptr, nullptr, Cv, Cv);
}

// round 16
// speedup vs baseline: 1.0404x; 1.0148x over previous
#include <cuda_runtime.h>
#include <cuda_fp16.h>
#include <math.h>
#include <stdint.h>

// Problem constants: B=4, T=2048, C=768, H=12, D=64
#define Bv 4
#define Tv 2048
#define Cv 768
#define Hv 12
#define Dv 64
#define C3v (3 * Cv)     // 2304
#define Mv (Bv * Tv)     // 8192

// ---------------- device scratch (no allocation allowed) -------------------
__device__ __half g_x16[(size_t)Mv * Cv];
__device__ __half g_wA[(size_t)C3v * Cv];     // transposed [3C, C] fp16
__device__ __half g_wP[(size_t)Cv * Cv];      // transposed [C, C] fp16
__device__ __half g_q16[(size_t)Mv * Cv];     // [b,h,t,d], pre-scaled by 1/8
__device__ __half g_k16[(size_t)Mv * Cv];     // [b,h,t,d]
__device__ __half g_vt16[(size_t)Mv * Cv];    // [b,h,d,t]  (V transposed)
__device__ __half g_y16[(size_t)Mv * Cv];     // [b,t,h*d]

// ---------------------------------------------------------------------------
__device__ __forceinline__ void mma16816(float* c, const uint32_t* a,
                                         uint32_t b0, uint32_t b1) {
    asm volatile(
        "mma.sync.aligned.m16n8k16.row.col.f32.f16.f16.f32 "
        "{%0,%1,%2,%3}, {%4,%5,%6,%7}, {%8,%9}, {%0,%1,%2,%3};"
        : "+f"(c[0]), "+f"(c[1]), "+f"(c[2]), "+f"(c[3])
        : "r"(a[0]), "r"(a[1]), "r"(a[2]), "r"(a[3]), "r"(b0), "r"(b1));
}

__device__ __forceinline__ void ldsm4(uint32_t* r, uint32_t addr) {
    asm volatile("ldmatrix.sync.aligned.m8n8.x4.shared.b16 {%0,%1,%2,%3}, [%4];"
        : "=r"(r[0]), "=r"(r[1]), "=r"(r[2]), "=r"(r[3]) : "r"(addr));
}

__device__ __forceinline__ uint32_t smem_u32(const void* p) {
    uint32_t a;
    asm("{ .reg .u64 t; cvta.to.shared.u64 t, %1; cvt.u32.u64 %0, t; }" : "=r"(a) : "l"(p));
    return a;
}
#define CP16(dst, src) \
    asm volatile("cp.async.cg.shared.global [%0], [%1], 16;" :: "r"(dst), "l"(src))
#define CP_COMMIT() asm volatile("cp.async.commit_group;" ::: "memory")
#define CP_WAIT1()  asm volatile("cp.async.wait_group 1;" ::: "memory")

__device__ __forceinline__ uint32_t pack_h(float a, float b) {
    __half2 t;
    t.x = __float2half_rn(a);
    t.y = __float2half_rn(b);
    return *(uint32_t*)&t;
}

// ---------------------------------------------------------------------------
// Fused prep: one launch does x->fp16 convert + both weight transposes.
// ---------------------------------------------------------------------------
#define PX   (Mv * Cv / 1024)              // 6144
#define PWA  ((C3v / 32) * (Cv / 32))      // 1728
#define PWP  ((Cv / 32) * (Cv / 32))       // 576
#define PREP_BLOCKS (PX + PWA + PWP)       // 8448

__global__ void prep_kernel(const float* __restrict__ x, __half* __restrict__ x16,
                            const float* __restrict__ wA, __half* __restrict__ wA16,
                            const float* __restrict__ wP, __half* __restrict__ wP16) {
    __shared__ float st[32][33];
    int blk = blockIdx.x;
    if (blk < PX) {
        const int i = (blk * 256 + threadIdx.x) * 4;
        float4 v = *(const float4*)(x + i);
        *(uint32_t*)(x16 + i)     = pack_h(v.x, v.y);
        *(uint32_t*)(x16 + i + 2) = pack_h(v.z, v.w);
        return;
    }
    blk -= PX;
    const float* w;
    __half* t_;
    int N, nbx;
    if (blk < PWA) { w = wA; t_ = wA16; N = C3v; nbx = C3v / 32; }
    else           { blk -= PWA; w = wP; t_ = wP16; N = Cv; nbx = Cv / 32; }
    const int K = Cv;
    const int n0 = (blk % nbx) * 32, k0 = (blk / nbx) * 32;
    const int tx = threadIdx.x & 31, ty = threadIdx.x >> 5;   // (32, 8)
    #pragma unroll
    for (int i = 0; i < 4; i++)
        st[ty + 8 * i][tx] = w[(size_t)(k0 + ty + 8 * i) * N + n0 + tx];
    __syncthreads();
    #pragma unroll
    for (int i = 0; i < 4; i++)
        t_[(size_t)(n0 + ty + 8 * i) * K + k0 + tx] =
            __float2half_rn(st[tx][ty + 8 * i]);
}

// ---------------------------------------------------------------------------
// fp16 GEMM: 128x64 tile, BK=64, 8 warps (4Mx2N), 3-stage cp.async,
// software-pipelined ldmatrix (1-step lookahead), 2 CTAs/SM.
// MODE 0: C = A@B^T + bias -> fp32. MODE 1: QKV scatter epilogue.
// ---------------------------------------------------------------------------
#define GRS 72
#define GTA_BYTES 18432                // A tile: 128 * 72 * 2
#define GTB_BYTES 9216                 // B tile:  64 * 72 * 2
#define GB_OFF    (3 * GTA_BYTES)      // 55296
#define G_SMEM    (GB_OFF + 3 * GTB_BYTES)   // 82944

template <int MODE>
__global__ __launch_bounds__(256, 2)
void gemm_mma(const __half* __restrict__ Am, const __half* __restrict__ Bm,
              const float* __restrict__ bias, float* __restrict__ Cmat,
              __half* __restrict__ q16, __half* __restrict__ k16,
              __half* __restrict__ vt16, int N, int K) {
    extern __shared__ __align__(16) char gsm[];
    const uint32_t sb = smem_u32(gsm);

    const int tid = threadIdx.x;
    const int wid = tid >> 5, lane = tid & 31;
    const int g = lane >> 2, tig = lane & 3;
    const int bx = blockIdx.x, by = blockIdx.y;
    const int wm = (wid & 3) * 32;
    const int wn = (wid >> 2) * 32;

    const int aRow = lane & 15, aCol8 = (lane >> 4) * 8;
    const int bRow = ((lane >> 4) * 8) + (lane & 7);
    const int bCol8 = ((lane >> 3) & 1) * 8;

    float acc[2][4][4];
    #pragma unroll
    for (int mt = 0; mt < 2; mt++)
        #pragma unroll
        for (int nt = 0; nt < 4; nt++)
            #pragma unroll
            for (int j = 0; j < 4; j++) acc[mt][nt][j] = 0.f;

    const int nCh = K >> 6;                     // BK = 64

    auto load_chunk = [&](int c, int s) {
        const int k0 = c << 6;
        #pragma unroll
        for (int i = 0; i < 4; i++) {
            const int u = tid + i * 256;
            const int r = u >> 3, c8 = (u & 7) * 8;
            const size_t ga = (size_t)(by * 128 + r) * K + k0 + c8;
            CP16(sb + s * GTA_BYTES + (uint32_t)(r * 144 + c8 * 2), Am + ga);
        }
        #pragma unroll
        for (int i = 0; i < 2; i++) {
            const int u = tid + i * 256;
            const int r = u >> 3, c8 = (u & 7) * 8;
            const size_t gb = (size_t)(bx * 64 + r) * K + k0 + c8;
            CP16(sb + GB_OFF + s * GTB_BYTES + (uint32_t)(r * 144 + c8 * 2), Bm + gb);
        }
    };

    load_chunk(0, 0); CP_COMMIT();
    load_chunk(1, 1); CP_COMMIT();

    int s = 0;
    for (int c = 0; c < nCh; c++) {
        CP_WAIT1();
        __syncthreads();
        if (c + 2 < nCh) {
            const int s2 = (s + 2 >= 3) ? s - 1 : s + 2;
            load_chunk(c + 2, s2);
        }
        CP_COMMIT();

        const uint32_t abase = sb + s * GTA_BYTES;
        const uint32_t bbase = sb + GB_OFF + s * GTB_BYTES;

        // software-pipelined fragment loads: 8 steps = (ks, p), lookahead 1
        uint32_t afr[2][2][4];     // [bank][mt][4]
        uint32_t bfr[2][4];        // [bank][4]
        ldsm4(afr[0][0], abase + ((wm + aRow) * GRS + aCol8) * 2);
        ldsm4(afr[0][1], abase + ((wm + 16 + aRow) * GRS + aCol8) * 2);
        ldsm4(bfr[0],    bbase + ((wn + bRow) * GRS + bCol8) * 2);
        #pragma unroll
        for (int st = 0; st < 8; st++) {
            const int ks = st >> 1, p = st & 1;
            const int ab = ks & 1, bb = st & 1;
            if (st + 1 < 8) {
                const int nks = (st + 1) >> 1, np = (st + 1) & 1;
                const int nab = nks & 1, nbb = (st + 1) & 1;
                if (np == 0) {
                    ldsm4(afr[nab][0], abase +
                          ((wm + aRow) * GRS + nks * 16 + aCol8) * 2);
                    ldsm4(afr[nab][1], abase +
                          ((wm + 16 + aRow) * GRS + nks * 16 + aCol8) * 2);
                }
                ldsm4(bfr[nbb], bbase +
                      ((wn + np * 16 + bRow) * GRS + nks * 16 + bCol8) * 2);
            }
            mma16816(acc[0][2 * p],     afr[ab][0], bfr[bb][0], bfr[bb][1]);
            mma16816(acc[1][2 * p],     afr[ab][1], bfr[bb][0], bfr[bb][1]);
            mma16816(acc[0][2 * p + 1], afr[ab][0], bfr[bb][2], bfr[bb][3]);
            mma16816(acc[1][2 * p + 1], afr[ab][1], bfr[bb][2], bfr[bb][3]);
        }
        s = (s + 1 == 3) ? 0 : s + 1;
    }

    if (MODE == 0) {
        #pragma unroll
        for (int mt = 0; mt < 2; mt++) {
            #pragma unroll
            for (int nt = 0; nt < 4; nt++) {
                const int rg = by * 128 + wm + mt * 16 + g;
                const int cg = bx * 64 + wn + nt * 8 + tig * 2;
                const float bs0 = __ldg(bias + cg), bs1 = __ldg(bias + cg + 1);
                float2 v0, v1;
                v0.x = acc[mt][nt][0] + bs0;
                v0.y = acc[mt][nt][1] + bs1;
                v1.x = acc[mt][nt][2] + bs0;
                v1.y = acc[mt][nt][3] + bs1;
                *(float2*)(Cmat + (size_t)rg * N + cg)       = v0;
                *(float2*)(Cmat + (size_t)(rg + 8) * N + cg) = v1;
            }
        }
    } else {
        const int reg3 = bx / Hv;       // 0=Q, 1=K, 2=V
        const int h    = bx % Hv;
        #pragma unroll
        for (int mt = 0; mt < 2; mt++) {
            #pragma unroll
            for (int nt = 0; nt < 4; nt++) {
                const int rg = by * 128 + wm + mt * 16 + g;
                const int bb = rg >> 11, t = rg & 2047;
                const int d = wn + nt * 8 + tig * 2;
                const int cg = bx * 64 + d;
                const float bs0 = __ldg(bias + cg), bs1 = __ldg(bias + cg + 1);
                const float v0 = acc[mt][nt][0] + bs0;
                const float v1 = acc[mt][nt][1] + bs1;
                const float v2 = acc[mt][nt][2] + bs0;
                const float v3 = acc[mt][nt][3] + bs1;
                if (reg3 == 0) {
                    const size_t o = ((size_t)(bb * Hv + h) * Tv + t) * Dv + d;
                    *(uint32_t*)(q16 + o)           = pack_h(v0 * 0.125f, v1 * 0.125f);
                    *(uint32_t*)(q16 + o + 8 * Dv)  = pack_h(v2 * 0.125f, v3 * 0.125f);
                } else if (reg3 == 1) {
                    const size_t o = ((size_t)(bb * Hv + h) * Tv + t) * Dv + d;
                    *(uint32_t*)(k16 + o)           = pack_h(v0, v1);
                    *(uint32_t*)(k16 + o + 8 * Dv)  = pack_h(v2, v3);
                } else {
                    const size_t o = ((size_t)(bb * Hv + h) * Dv + d) * Tv + t;
                    vt16[o]          = __float2half_rn(v0);
                    vt16[o + Tv]     = __float2half_rn(v1);
                    vt16[o + 8]      = __float2half_rn(v2);
                    vt16[o + Tv + 8] = __float2half_rn(v3);
                }
            }
        }
    }
}

// ---------------------------------------------------------------------------
// fp16 causal flash attention, 3-stage cp.async, software-pipelined ldmatrix.
// ---------------------------------------------------------------------------
#define AKS 72               // smem row stride (fp16)
#define AT_BYTES 9216        // 64 * 72 * 2
#define A_OFF_K 0                      // 3 stages
#define A_OFF_V (3 * AT_BYTES)         // 3 stages
#define A_SMEM  (6 * AT_BYTES)         // 55296

__global__ __launch_bounds__(256, 2)
void attn_mma(const __half* __restrict__ q16, const __half* __restrict__ k16,
              const __half* __restrict__ vt16, __half* __restrict__ y16) {
    extern __shared__ char sm[];
    const uint32_t sbase = smem_u32(sm);

    const int qt = (gridDim.x - 1) - blockIdx.x;   // heavy blocks first
    const int h  = blockIdx.y;
    const int b  = blockIdx.z;
    const int tid = threadIdx.x;
    const int wid = tid >> 5, lane = tid & 31;
    const int g = lane >> 2, tig = lane & 3;

    const int bRow = ((lane >> 4) * 8) + (lane & 7);
    const int bCol8 = ((lane >> 3) & 1) * 8;

    const int qr0 = qt * 128;
    const int row0 = qr0 + wid * 16 + g;
    const int warpRowMax = qr0 + wid * 16 + 15;
    const size_t qb  = (size_t)(b * Hv + h) * Tv * Dv;
    const size_t vtb = (size_t)(b * Hv + h) * Dv * Tv;

    auto load_kv = [&](int kvb, int s) {
        const int kv0 = kvb * 64;
        #pragma unroll
        for (int i = 0; i < 2; i++) {
            const int u = tid + i * 256;
            const int r = u >> 3, c8 = (u & 7) * 8;
            CP16(sbase + A_OFF_K + s * AT_BYTES + (uint32_t)(r * 144 + c8 * 2),
                 k16 + qb + (size_t)(kv0 + r) * Dv + c8);
            CP16(sbase + A_OFF_V + s * AT_BYTES + (uint32_t)(r * 144 + c8 * 2),
                 vt16 + vtb + (size_t)r * Tv + kv0 + c8);
        }
    };

    uint32_t qh[4][4];
    #pragma unroll
    for (int ks = 0; ks < 4; ks++) {
        const int kc = ks * 16 + tig * 2;
        #pragma unroll
        for (int j = 0; j < 4; j++) {
            const int rr = (j & 1) ? row0 + 8 : row0;
            const int cc = kc + ((j >> 1) ? 8 : 0);
            qh[ks][j] = *(const uint32_t*)(q16 + qb + (size_t)rr * Dv + cc);
        }
    }

    float acc_o[8][4];
    #pragma unroll
    for (int nt = 0; nt < 8; nt++)
        #pragma unroll
        for (int j = 0; j < 4; j++) acc_o[nt][j] = 0.f;
    float m0 = -INFINITY, m1 = -INFINITY, l0 = 0.f, l1 = 0.f;

    const int nkv = (qr0 >> 6) + 2;
    load_kv(0, 0); CP_COMMIT();
    load_kv(1, 1); CP_COMMIT();

    int s = 0;
    for (int kvb = 0; kvb < nkv; kvb++) {
        const int kv0 = kvb * 64;
        CP_WAIT1();
        __syncthreads();
        if (kvb + 2 < nkv) {
            const int s2 = (s + 2 >= 3) ? s - 1 : s + 2;
            load_kv(kvb + 2, s2);
        }
        CP_COMMIT();

        if (kv0 <= warpRowMax) {
            const uint32_t kbase = sbase + A_OFF_K + s * AT_BYTES;
            const uint32_t vbase = sbase + A_OFF_V + s * AT_BYTES;
            float s_[8][4];
            #pragma unroll
            for (int nt = 0; nt < 8; nt++)
                #pragma unroll
                for (int j = 0; j < 4; j++) s_[nt][j] = 0.f;

            // S = Q K^T : 16 pipelined steps (ks major, p minor)
            {
                uint32_t bfr[2][4];
                ldsm4(bfr[0], kbase + (bRow * AKS + bCol8) * 2);
                #pragma unroll
                for (int st = 0; st < 16; st++) {
                    const int ks = st >> 2, p = st & 3;
                    if (st + 1 < 16) {
                        const int nks = (st + 1) >> 2, np = (st + 1) & 3;
                        ldsm4(bfr[(st + 1) & 1], kbase +
                              ((np * 16 + bRow) * AKS + nks * 16 + bCol8) * 2);
                    }
                    mma16816(s_[2 * p],     qh[ks], bfr[st & 1][0], bfr[st & 1][1]);
                    mma16816(s_[2 * p + 1], qh[ks], bfr[st & 1][2], bfr[st & 1][3]);
                }
            }

            float rmax0 = -INFINITY, rmax1 = -INFINITY;
            #pragma unroll
            for (int nt = 0; nt < 8; nt++) {
                const int colb = kv0 + nt * 8 + tig * 2;
                #pragma unroll
                for (int j = 0; j < 2; j++) {
                    if (colb + j > row0)     s_[nt][j]     = -INFINITY;
                    if (colb + j > row0 + 8) s_[nt][2 + j] = -INFINITY;
                    rmax0 = fmaxf(rmax0, s_[nt][j]);
                    rmax1 = fmaxf(rmax1, s_[nt][2 + j]);
                }
            }
            rmax0 = fmaxf(rmax0, __shfl_xor_sync(0xffffffff, rmax0, 1));
            rmax0 = fmaxf(rmax0, __shfl_xor_sync(0xffffffff, rmax0, 2));
            rmax1 = fmaxf(rmax1, __shfl_xor_sync(0xffffffff, rmax1, 1));
            rmax1 = fmaxf(rmax1, __shfl_xor_sync(0xffffffff, rmax1, 2));

            const float mn0 = fmaxf(m0, rmax0);
            const float mn1 = fmaxf(m1, rmax1);
            const float cr0 = __expf(m0 - mn0);
            const float cr1 = __expf(m1 - mn1);
            l0 *= cr0; l1 *= cr1;
            #pragma unroll
            for (int nt = 0; nt < 8; nt++) {
                acc_o[nt][0] *= cr0; acc_o[nt][1] *= cr0;
                acc_o[nt][2] *= cr1; acc_o[nt][3] *= cr1;
            }
            m0 = mn0; m1 = mn1;

            uint32_t ph[4][4];
            float rs0 = 0.f, rs1 = 0.f;
            #pragma unroll
            for (int kt = 0; kt < 4; kt++) {
                float p00, p01, p10, p11;
                p00 = __expf(s_[2 * kt][0] - mn0);
                p01 = __expf(s_[2 * kt][1] - mn0);
                p10 = __expf(s_[2 * kt][2] - mn1);
                p11 = __expf(s_[2 * kt][3] - mn1);
                rs0 += p00 + p01; rs1 += p10 + p11;
                ph[kt][0] = pack_h(p00, p01);
                ph[kt][1] = pack_h(p10, p11);
                p00 = __expf(s_[2 * kt + 1][0] - mn0);
                p01 = __expf(s_[2 * kt + 1][1] - mn0);
                p10 = __expf(s_[2 * kt + 1][2] - mn1);
                p11 = __expf(s_[2 * kt + 1][3] - mn1);
                rs0 += p00 + p01; rs1 += p10 + p11;
                ph[kt][2] = pack_h(p00, p01);
                ph[kt][3] = pack_h(p10, p11);
            }
            rs0 += __shfl_xor_sync(0xffffffff, rs0, 1);
            rs0 += __shfl_xor_sync(0xffffffff, rs0, 2);
            rs1 += __shfl_xor_sync(0xffffffff, rs1, 1);
            rs1 += __shfl_xor_sync(0xffffffff, rs1, 2);
            l0 += rs0; l1 += rs1;

            // O += P V : 16 pipelined steps (kt major, p minor)
            {
                uint32_t bfr[2][4];
                ldsm4(bfr[0], vbase + (bRow * AKS + bCol8) * 2);
                #pragma unroll
                for (int st = 0; st < 16; st++) {
                    const int kt = st >> 2, p = st & 3;
                    if (st + 1 < 16) {
                        const int nkt = (st + 1) >> 2, np = (st + 1) & 3;
                        ldsm4(bfr[(st + 1) & 1], vbase +
                              ((np * 16 + bRow) * AKS + nkt * 16 + bCol8) * 2);
                    }
                    mma16816(acc_o[2 * p],     ph[kt], bfr[st & 1][0], bfr[st & 1][1]);
                    mma16816(acc_o[2 * p + 1], ph[kt], bfr[st & 1][2], bfr[st & 1][3]);
                }
            }
        }
        s = (s + 1 == 3) ? 0 : s + 1;
    }

    const float i0 = 1.f / l0, i1 = 1.f / l1;
    #pragma unroll
    for (int nt = 0; nt < 8; nt++) {
        const int d = nt * 8 + tig * 2;
        const size_t o0 = ((size_t)b * Tv + row0) * Cv + h * Dv + d;
        const size_t o1 = o0 + (size_t)8 * Cv;
        *(uint32_t*)(y16 + o0) = pack_h(acc_o[nt][0] * i0, acc_o[nt][1] * i0);
        *(uint32_t*)(y16 + o1) = pack_h(acc_o[nt][2] * i1, acc_o[nt][3] * i1);
    }
}

// ---------------------------------------------------------------------------
extern "C" void kernel_launch(void* const* d_in, const int* in_sizes, int n_in,
                              void* d_out, int out_size) {
    const float* x      = (const float*)d_in[0];
    const float* w_attn = (const float*)d_in[1];
    const float* b_attn = (const float*)d_in[2];
    const float* w_proj = (const float*)d_in[3];
    const float* b_proj = (const float*)d_in[4];
    float* out = (float*)d_out;

    __half *x16, *wA, *wP, *q16, *k16, *vt16, *y16;
    cudaGetSymbolAddress((void**)&x16, g_x16);
    cudaGetSymbolAddress((void**)&wA, g_wA);
    cudaGetSymbolAddress((void**)&wP, g_wP);
    cudaGetSymbolAddress((void**)&q16, g_q16);
    cudaGetSymbolAddress((void**)&k16, g_k16);
    cudaGetSymbolAddress((void**)&vt16, g_vt16);
    cudaGetSymbolAddress((void**)&y16, g_y16);

    cudaFuncSetAttribute(gemm_mma<0>, cudaFuncAttributeMaxDynamicSharedMemorySize, G_SMEM);
    cudaFuncSetAttribute(gemm_mma<1>, cudaFuncAttributeMaxDynamicSharedMemorySize, G_SMEM);
    cudaFuncSetAttribute(attn_mma, cudaFuncAttributeMaxDynamicSharedMemorySize, A_SMEM);

    // 0) fused prep: x->fp16 + both weight transposes (single launch)
    prep_kernel<<<PREP_BLOCKS, 256>>>(x, x16, w_attn, wA, w_proj, wP);

    // 1) QKV GEMM with fused scatter epilogue -> q16 (scaled), k16, vt16
    gemm_mma<1><<<dim3(C3v / 64, Mv / 128), 256, G_SMEM>>>(
        x16, wA, b_attn, nullptr, q16, k16, vt16, C3v, Cv);
    // 2) causal flash attention (all-fp16 operands, pipelined fragments)
    attn_mma<<<dim3(Tv / 128, Hv, Bv), 256, A_SMEM>>>(q16, k16, vt16, y16);
    // 3) out = y @ w_proj + b_proj (fp32 out)
    gemm_mma<0><<<dim3(Cv / 64, Mv / 128), 256, G_SMEM>>>(
        y16, wP, b_proj, out, nullptr, nullptr, nullptr, Cv, Cv);
}

// round 17
// speedup vs baseline: 1.0534x; 1.0124x over previous
#include <cuda_runtime.h>
#include <cuda_fp16.h>
#include <math.h>
#include <stdint.h>

// Problem constants: B=4, T=2048, C=768, H=12, D=64
#define Bv 4
#define Tv 2048
#define Cv 768
#define Hv 12
#define Dv 64
#define C3v (3 * Cv)     // 2304
#define Mv (Bv * Tv)     // 8192

// ---------------- device scratch (no allocation allowed) -------------------
__device__ __half g_x16[(size_t)Mv * Cv];
__device__ __half g_wA[(size_t)C3v * Cv];     // transposed [3C, C] fp16
__device__ __half g_wP[(size_t)Cv * Cv];      // transposed [C, C] fp16
__device__ __half g_q16[(size_t)Mv * Cv];     // [b,h,t,d], pre-scaled by 1/8
__device__ __half g_k16[(size_t)Mv * Cv];     // [b,h,t,d]
__device__ __half g_vt16[(size_t)Mv * Cv];    // [b,h,d,t]  (V transposed)
__device__ __half g_y16[(size_t)Mv * Cv];     // [b,t,h*d]

// ---------------------------------------------------------------------------
__device__ __forceinline__ void mma16816(float* c, const uint32_t* a,
                                         uint32_t b0, uint32_t b1) {
    asm volatile(
        "mma.sync.aligned.m16n8k16.row.col.f32.f16.f16.f32 "
        "{%0,%1,%2,%3}, {%4,%5,%6,%7}, {%8,%9}, {%0,%1,%2,%3};"
        : "+f"(c[0]), "+f"(c[1]), "+f"(c[2]), "+f"(c[3])
        : "r"(a[0]), "r"(a[1]), "r"(a[2]), "r"(a[3]), "r"(b0), "r"(b1));
}

__device__ __forceinline__ void ldsm4(uint32_t* r, uint32_t addr) {
    asm volatile("ldmatrix.sync.aligned.m8n8.x4.shared.b16 {%0,%1,%2,%3}, [%4];"
        : "=r"(r[0]), "=r"(r[1]), "=r"(r[2]), "=r"(r[3]) : "r"(addr));
}

__device__ __forceinline__ uint32_t smem_u32(const void* p) {
    uint32_t a;
    asm("{ .reg .u64 t; cvta.to.shared.u64 t, %1; cvt.u32.u64 %0, t; }" : "=r"(a) : "l"(p));
    return a;
}
#define CP16(dst, src) \
    asm volatile("cp.async.cg.shared.global [%0], [%1], 16;" :: "r"(dst), "l"(src))
#define CP_COMMIT() asm volatile("cp.async.commit_group;" ::: "memory")
#define CP_WAIT1()  asm volatile("cp.async.wait_group 1;" ::: "memory")
#define CP_WAIT2()  asm volatile("cp.async.wait_group 2;" ::: "memory")

__device__ __forceinline__ uint32_t pack_h(float a, float b) {
    __half2 t;
    t.x = __float2half_rn(a);
    t.y = __float2half_rn(b);
    return *(uint32_t*)&t;
}

// ---------------------------------------------------------------------------
// Fused prep: x->fp16 convert (MLP=4) + both weight transposes, one launch.
// ---------------------------------------------------------------------------
#define PX   (Mv * Cv / 4096)              // 1536 (4096 elems per block)
#define PWA  ((C3v / 32) * (Cv / 32))      // 1728
#define PWP  ((Cv / 32) * (Cv / 32))       // 576
#define PREP_BLOCKS (PX + PWA + PWP)       // 3840

__global__ void prep_kernel(const float* __restrict__ x, __half* __restrict__ x16,
                            const float* __restrict__ wA, __half* __restrict__ wA16,
                            const float* __restrict__ wP, __half* __restrict__ wP16) {
    __shared__ float st[32][33];
    int blk = blockIdx.x;
    if (blk < PX) {
        const int i0 = blk * 4096 + threadIdx.x * 4;
        float4 v[4];
        #pragma unroll
        for (int j = 0; j < 4; j++)                 // 4 independent loads (MLP=4)
            v[j] = *(const float4*)(x + i0 + j * 1024);
        #pragma unroll
        for (int j = 0; j < 4; j++) {
            *(uint32_t*)(x16 + i0 + j * 1024)     = pack_h(v[j].x, v[j].y);
            *(uint32_t*)(x16 + i0 + j * 1024 + 2) = pack_h(v[j].z, v[j].w);
        }
        return;
    }
    blk -= PX;
    const float* w;
    __half* t_;
    int N, nbx;
    if (blk < PWA) { w = wA; t_ = wA16; N = C3v; nbx = C3v / 32; }
    else           { blk -= PWA; w = wP; t_ = wP16; N = Cv; nbx = Cv / 32; }
    const int K = Cv;
    const int n0 = (blk % nbx) * 32, k0 = (blk / nbx) * 32;
    const int tx = threadIdx.x & 31, ty = threadIdx.x >> 5;   // (32, 8)
    #pragma unroll
    for (int i = 0; i < 4; i++)
        st[ty + 8 * i][tx] = w[(size_t)(k0 + ty + 8 * i) * N + n0 + tx];
    __syncthreads();
    #pragma unroll
    for (int i = 0; i < 4; i++)
        t_[(size_t)(n0 + ty + 8 * i) * K + k0 + tx] =
            __float2half_rn(st[tx][ty + 8 * i]);
}

// ---------------------------------------------------------------------------
// fp16 GEMM: 128x64 tile, BK=64, 8 warps (4Mx2N), 3-stage cp.async,
// software-pipelined ldmatrix (1-step lookahead), 2 CTAs/SM.
// MODE 0: C = A@B^T + bias -> fp32. MODE 1: QKV scatter epilogue.
// ---------------------------------------------------------------------------
#define GRS 72
#define GTA_BYTES 18432                // A tile: 128 * 72 * 2
#define GTB_BYTES 9216                 // B tile:  64 * 72 * 2
#define GB_OFF    (3 * GTA_BYTES)      // 55296
#define G_SMEM    (GB_OFF + 3 * GTB_BYTES)   // 82944

template <int MODE>
__global__ __launch_bounds__(256, 2)
void gemm_mma(const __half* __restrict__ Am, const __half* __restrict__ Bm,
              const float* __restrict__ bias, float* __restrict__ Cmat,
              __half* __restrict__ q16, __half* __restrict__ k16,
              __half* __restrict__ vt16, int N, int K) {
    extern __shared__ __align__(16) char gsm[];
    const uint32_t sb = smem_u32(gsm);

    const int tid = threadIdx.x;
    const int wid = tid >> 5, lane = tid & 31;
    const int g = lane >> 2, tig = lane & 3;
    const int bx = blockIdx.x, by = blockIdx.y;
    const int wm = (wid & 3) * 32;
    const int wn = (wid >> 2) * 32;

    const int aRow = lane & 15, aCol8 = (lane >> 4) * 8;
    const int bRow = ((lane >> 4) * 8) + (lane & 7);
    const int bCol8 = ((lane >> 3) & 1) * 8;

    float acc[2][4][4];
    #pragma unroll
    for (int mt = 0; mt < 2; mt++)
        #pragma unroll
        for (int nt = 0; nt < 4; nt++)
            #pragma unroll
            for (int j = 0; j < 4; j++) acc[mt][nt][j] = 0.f;

    const int nCh = K >> 6;                     // BK = 64

    auto load_chunk = [&](int c, int s) {
        const int k0 = c << 6;
        #pragma unroll
        for (int i = 0; i < 4; i++) {
            const int u = tid + i * 256;
            const int r = u >> 3, c8 = (u & 7) * 8;
            const size_t ga = (size_t)(by * 128 + r) * K + k0 + c8;
            CP16(sb + s * GTA_BYTES + (uint32_t)(r * 144 + c8 * 2), Am + ga);
        }
        #pragma unroll
        for (int i = 0; i < 2; i++) {
            const int u = tid + i * 256;
            const int r = u >> 3, c8 = (u & 7) * 8;
            const size_t gb = (size_t)(bx * 64 + r) * K + k0 + c8;
            CP16(sb + GB_OFF + s * GTB_BYTES + (uint32_t)(r * 144 + c8 * 2), Bm + gb);
        }
    };

    load_chunk(0, 0); CP_COMMIT();
    load_chunk(1, 1); CP_COMMIT();

    int s = 0;
    for (int c = 0; c < nCh; c++) {
        CP_WAIT1();
        __syncthreads();
        if (c + 2 < nCh) {
            const int s2 = (s + 2 >= 3) ? s - 1 : s + 2;
            load_chunk(c + 2, s2);
        }
        CP_COMMIT();

        const uint32_t abase = sb + s * GTA_BYTES;
        const uint32_t bbase = sb + GB_OFF + s * GTB_BYTES;

        uint32_t afr[2][2][4];     // [bank][mt][4]
        uint32_t bfr[2][4];        // [bank][4]
        ldsm4(afr[0][0], abase + ((wm + aRow) * GRS + aCol8) * 2);
        ldsm4(afr[0][1], abase + ((wm + 16 + aRow) * GRS + aCol8) * 2);
        ldsm4(bfr[0],    bbase + ((wn + bRow) * GRS + bCol8) * 2);
        #pragma unroll
        for (int st = 0; st < 8; st++) {
            const int ks = st >> 1, p = st & 1;
            const int ab = ks & 1, bb = st & 1;
            if (st + 1 < 8) {
                const int nks = (st + 1) >> 1, np = (st + 1) & 1;
                const int nab = nks & 1, nbb = (st + 1) & 1;
                if (np == 0) {
                    ldsm4(afr[nab][0], abase +
                          ((wm + aRow) * GRS + nks * 16 + aCol8) * 2);
                    ldsm4(afr[nab][1], abase +
                          ((wm + 16 + aRow) * GRS + nks * 16 + aCol8) * 2);
                }
                ldsm4(bfr[nbb], bbase +
                      ((wn + np * 16 + bRow) * GRS + nks * 16 + bCol8) * 2);
            }
            mma16816(acc[0][2 * p],     afr[ab][0], bfr[bb][0], bfr[bb][1]);
            mma16816(acc[1][2 * p],     afr[ab][1], bfr[bb][0], bfr[bb][1]);
            mma16816(acc[0][2 * p + 1], afr[ab][0], bfr[bb][2], bfr[bb][3]);
            mma16816(acc[1][2 * p + 1], afr[ab][1], bfr[bb][2], bfr[bb][3]);
        }
        s = (s + 1 == 3) ? 0 : s + 1;
    }

    if (MODE == 0) {
        #pragma unroll
        for (int mt = 0; mt < 2; mt++) {
            #pragma unroll
            for (int nt = 0; nt < 4; nt++) {
                const int rg = by * 128 + wm + mt * 16 + g;
                const int cg = bx * 64 + wn + nt * 8 + tig * 2;
                const float bs0 = __ldg(bias + cg), bs1 = __ldg(bias + cg + 1);
                float2 v0, v1;
                v0.x = acc[mt][nt][0] + bs0;
                v0.y = acc[mt][nt][1] + bs1;
                v1.x = acc[mt][nt][2] + bs0;
                v1.y = acc[mt][nt][3] + bs1;
                *(float2*)(Cmat + (size_t)rg * N + cg)       = v0;
                *(float2*)(Cmat + (size_t)(rg + 8) * N + cg) = v1;
            }
        }
    } else {
        const int reg3 = bx / Hv;       // 0=Q, 1=K, 2=V
        const int h    = bx % Hv;
        #pragma unroll
        for (int mt = 0; mt < 2; mt++) {
            #pragma unroll
            for (int nt = 0; nt < 4; nt++) {
                const int rg = by * 128 + wm + mt * 16 + g;
                const int bb = rg >> 11, t = rg & 2047;
                const int d = wn + nt * 8 + tig * 2;
                const int cg = bx * 64 + d;
                const float bs0 = __ldg(bias + cg), bs1 = __ldg(bias + cg + 1);
                const float v0 = acc[mt][nt][0] + bs0;
                const float v1 = acc[mt][nt][1] + bs1;
                const float v2 = acc[mt][nt][2] + bs0;
                const float v3 = acc[mt][nt][3] + bs1;
                if (reg3 == 0) {
                    const size_t o = ((size_t)(bb * Hv + h) * Tv + t) * Dv + d;
                    *(uint32_t*)(q16 + o)           = pack_h(v0 * 0.125f, v1 * 0.125f);
                    *(uint32_t*)(q16 + o + 8 * Dv)  = pack_h(v2 * 0.125f, v3 * 0.125f);
                } else if (reg3 == 1) {
                    const size_t o = ((size_t)(bb * Hv + h) * Tv + t) * Dv + d;
                    *(uint32_t*)(k16 + o)           = pack_h(v0, v1);
                    *(uint32_t*)(k16 + o + 8 * Dv)  = pack_h(v2, v3);
                } else {
                    const size_t o = ((size_t)(bb * Hv + h) * Dv + d) * Tv + t;
                    vt16[o]          = __float2half_rn(v0);
                    vt16[o + Tv]     = __float2half_rn(v1);
                    vt16[o + 8]      = __float2half_rn(v2);
                    vt16[o + Tv + 8] = __float2half_rn(v3);
                }
            }
        }
    }
}

// ---------------------------------------------------------------------------
// fp16 causal flash attention, 4-stage cp.async, software-pipelined ldmatrix.
// ---------------------------------------------------------------------------
#define AKS 72               // smem row stride (fp16)
#define AT_BYTES 9216        // 64 * 72 * 2
#define A_OFF_K 0                      // 4 stages
#define A_OFF_V (4 * AT_BYTES)         // 4 stages
#define A_SMEM  (8 * AT_BYTES)         // 73728

__global__ __launch_bounds__(256, 2)
void attn_mma(const __half* __restrict__ q16, const __half* __restrict__ k16,
              const __half* __restrict__ vt16, __half* __restrict__ y16) {
    extern __shared__ char sm[];
    const uint32_t sbase = smem_u32(sm);

    const int qt = (gridDim.x - 1) - blockIdx.x;   // heavy blocks first
    const int h  = blockIdx.y;
    const int b  = blockIdx.z;
    const int tid = threadIdx.x;
    const int wid = tid >> 5, lane = tid & 31;
    const int g = lane >> 2, tig = lane & 3;

    const int bRow = ((lane >> 4) * 8) + (lane & 7);
    const int bCol8 = ((lane >> 3) & 1) * 8;

    const int qr0 = qt * 128;
    const int row0 = qr0 + wid * 16 + g;
    const int warpRowMax = qr0 + wid * 16 + 15;
    const size_t qb  = (size_t)(b * Hv + h) * Tv * Dv;
    const size_t vtb = (size_t)(b * Hv + h) * Dv * Tv;

    auto load_kv = [&](int kvb, int s) {
        const int kv0 = kvb * 64;
        #pragma unroll
        for (int i = 0; i < 2; i++) {
            const int u = tid + i * 256;
            const int r = u >> 3, c8 = (u & 7) * 8;
            CP16(sbase + A_OFF_K + s * AT_BYTES + (uint32_t)(r * 144 + c8 * 2),
                 k16 + qb + (size_t)(kv0 + r) * Dv + c8);
            CP16(sbase + A_OFF_V + s * AT_BYTES + (uint32_t)(r * 144 + c8 * 2),
                 vt16 + vtb + (size_t)r * Tv + kv0 + c8);
        }
    };

    uint32_t qh[4][4];
    #pragma unroll
    for (int ks = 0; ks < 4; ks++) {
        const int kc = ks * 16 + tig * 2;
        #pragma unroll
        for (int j = 0; j < 4; j++) {
            const int rr = (j & 1) ? row0 + 8 : row0;
            const int cc = kc + ((j >> 1) ? 8 : 0);
            qh[ks][j] = *(const uint32_t*)(q16 + qb + (size_t)rr * Dv + cc);
        }
    }

    float acc_o[8][4];
    #pragma unroll
    for (int nt = 0; nt < 8; nt++)
        #pragma unroll
        for (int j = 0; j < 4; j++) acc_o[nt][j] = 0.f;
    float m0 = -INFINITY, m1 = -INFINITY, l0 = 0.f, l1 = 0.f;

    const int nkv = (qr0 >> 6) + 2;
    load_kv(0, 0); CP_COMMIT();
    if (nkv > 1) load_kv(1, 1);
    CP_COMMIT();
    if (nkv > 2) load_kv(2, 2);
    CP_COMMIT();

    int s = 0;
    for (int kvb = 0; kvb < nkv; kvb++) {
        const int kv0 = kvb * 64;
        CP_WAIT2();
        __syncthreads();
        if (kvb + 3 < nkv) load_kv(kvb + 3, (s + 3) & 3);
        CP_COMMIT();

        if (kv0 <= warpRowMax) {
            const uint32_t kbase = sbase + A_OFF_K + s * AT_BYTES;
            const uint32_t vbase = sbase + A_OFF_V + s * AT_BYTES;
            float s_[8][4];
            #pragma unroll
            for (int nt = 0; nt < 8; nt++)
                #pragma unroll
                for (int j = 0; j < 4; j++) s_[nt][j] = 0.f;

            // S = Q K^T : 16 pipelined steps
            {
                uint32_t bfr[2][4];
                ldsm4(bfr[0], kbase + (bRow * AKS + bCol8) * 2);
                #pragma unroll
                for (int st = 0; st < 16; st++) {
                    const int ks = st >> 2, p = st & 3;
                    if (st + 1 < 16) {
                        const int nks = (st + 1) >> 2, np = (st + 1) & 3;
                        ldsm4(bfr[(st + 1) & 1], kbase +
                              ((np * 16 + bRow) * AKS + nks * 16 + bCol8) * 2);
                    }
                    mma16816(s_[2 * p],     qh[ks], bfr[st & 1][0], bfr[st & 1][1]);
                    mma16816(s_[2 * p + 1], qh[ks], bfr[st & 1][2], bfr[st & 1][3]);
                }
            }

            float rmax0 = -INFINITY, rmax1 = -INFINITY;
            #pragma unroll
            for (int nt = 0; nt < 8; nt++) {
                const int colb = kv0 + nt * 8 + tig * 2;
                #pragma unroll
                for (int j = 0; j < 2; j++) {
                    if (colb + j > row0)     s_[nt][j]     = -INFINITY;
                    if (colb + j > row0 + 8) s_[nt][2 + j] = -INFINITY;
                    rmax0 = fmaxf(rmax0, s_[nt][j]);
                    rmax1 = fmaxf(rmax1, s_[nt][2 + j]);
                }
            }
            rmax0 = fmaxf(rmax0, __shfl_xor_sync(0xffffffff, rmax0, 1));
            rmax0 = fmaxf(rmax0, __shfl_xor_sync(0xffffffff, rmax0, 2));
            rmax1 = fmaxf(rmax1, __shfl_xor_sync(0xffffffff, rmax1, 1));
            rmax1 = fmaxf(rmax1, __shfl_xor_sync(0xffffffff, rmax1, 2));

            const float mn0 = fmaxf(m0, rmax0);
            const float mn1 = fmaxf(m1, rmax1);
            const float cr0 = __expf(m0 - mn0);
            const float cr1 = __expf(m1 - mn1);
            l0 *= cr0; l1 *= cr1;
            #pragma unroll
            for (int nt = 0; nt < 8; nt++) {
                acc_o[nt][0] *= cr0; acc_o[nt][1] *= cr0;
                acc_o[nt][2] *= cr1; acc_o[nt][3] *= cr1;
            }
            m0 = mn0; m1 = mn1;

            uint32_t ph[4][4];
            float rs0 = 0.f, rs1 = 0.f;
            #pragma unroll
            for (int kt = 0; kt < 4; kt++) {
                float p00, p01, p10, p11;
                p00 = __expf(s_[2 * kt][0] - mn0);
                p01 = __expf(s_[2 * kt][1] - mn0);
                p10 = __expf(s_[2 * kt][2] - mn1);
                p11 = __expf(s_[2 * kt][3] - mn1);
                rs0 += p00 + p01; rs1 += p10 + p11;
                ph[kt][0] = pack_h(p00, p01);
                ph[kt][1] = pack_h(p10, p11);
                p00 = __expf(s_[2 * kt + 1][0] - mn0);
                p01 = __expf(s_[2 * kt + 1][1] - mn0);
                p10 = __expf(s_[2 * kt + 1][2] - mn1);
                p11 = __expf(s_[2 * kt + 1][3] - mn1);
                rs0 += p00 + p01; rs1 += p10 + p11;
                ph[kt][2] = pack_h(p00, p01);
                ph[kt][3] = pack_h(p10, p11);
            }
            rs0 += __shfl_xor_sync(0xffffffff, rs0, 1);
            rs0 += __shfl_xor_sync(0xffffffff, rs0, 2);
            rs1 += __shfl_xor_sync(0xffffffff, rs1, 1);
            rs1 += __shfl_xor_sync(0xffffffff, rs1, 2);
            l0 += rs0; l1 += rs1;

            // O += P V : 16 pipelined steps
            {
                uint32_t bfr[2][4];
                ldsm4(bfr[0], vbase + (bRow * AKS + bCol8) * 2);
                #pragma unroll
                for (int st = 0; st < 16; st++) {
                    const int kt = st >> 2, p = st & 3;
                    if (st + 1 < 16) {
                        const int nkt = (st + 1) >> 2, np = (st + 1) & 3;
                        ldsm4(bfr[(st + 1) & 1], vbase +
                              ((np * 16 + bRow) * AKS + nkt * 16 + bCol8) * 2);
                    }
                    mma16816(acc_o[2 * p],     ph[kt], bfr[st & 1][0], bfr[st & 1][1]);
                    mma16816(acc_o[2 * p + 1], ph[kt], bfr[st & 1][2], bfr[st & 1][3]);
                }
            }
        }
        s = (s + 1) & 3;
    }

    const float i0 = 1.f / l0, i1 = 1.f / l1;
    #pragma unroll
    for (int nt = 0; nt < 8; nt++) {
        const int d = nt * 8 + tig * 2;
        const size_t o0 = ((size_t)b * Tv + row0) * Cv + h * Dv + d;
        const size_t o1 = o0 + (size_t)8 * Cv;
        *(uint32_t*)(y16 + o0) = pack_h(acc_o[nt][0] * i0, acc_o[nt][1] * i0);
        *(uint32_t*)(y16 + o1) = pack_h(acc_o[nt][2] * i1, acc_o[nt][3] * i1);
    }
}

// ---------------------------------------------------------------------------
extern "C" void kernel_launch(void* const* d_in, const int* in_sizes, int n_in,
                              void* d_out, int out_size) {
    const float* x      = (const float*)d_in[0];
    const float* w_attn = (const float*)d_in[1];
    const float* b_attn = (const float*)d_in[2];
    const float* w_proj = (const float*)d_in[3];
    const float* b_proj = (const float*)d_in[4];
    float* out = (float*)d_out;

    __half *x16, *wA, *wP, *q16, *k16, *vt16, *y16;
    cudaGetSymbolAddress((void**)&x16, g_x16);
    cudaGetSymbolAddress((void**)&wA, g_wA);
    cudaGetSymbolAddress((void**)&wP, g_wP);
    cudaGetSymbolAddress((void**)&q16, g_q16);
    cudaGetSymbolAddress((void**)&k16, g_k16);
    cudaGetSymbolAddress((void**)&vt16, g_vt16);
    cudaGetSymbolAddress((void**)&y16, g_y16);

    cudaFuncSetAttribute(gemm_mma<0>, cudaFuncAttributeMaxDynamicSharedMemorySize, G_SMEM);
    cudaFuncSetAttribute(gemm_mma<1>, cudaFuncAttributeMaxDynamicSharedMemorySize, G_SMEM);
    cudaFuncSetAttribute(attn_mma, cudaFuncAttributeMaxDynamicSharedMemorySize, A_SMEM);

    // 0) fused prep: x->fp16 (MLP=4) + both weight transposes (single launch)
    prep_kernel<<<PREP_BLOCKS, 256>>>(x, x16, w_attn, wA, w_proj, wP);

    // 1) QKV GEMM with fused scatter epilogue -> q16 (scaled), k16, vt16
    gemm_mma<1><<<dim3(C3v / 64, Mv / 128), 256, G_SMEM>>>(
        x16, wA, b_attn, nullptr, q16, k16, vt16, C3v, Cv);
    // 2) causal flash attention (all-fp16 operands, 4-stage pipeline)
    attn_mma<<<dim3(Tv / 128, Hv, Bv), 256, A_SMEM>>>(q16, k16, vt16, y16);
    // 3) out = y @ w_proj + b_proj (fp32 out)
    gemm_mma<0><<<dim3(Cv / 64, Mv / 128), 256, G_SMEM>>>(
        y16, wP, b_proj, out, nullptr, nullptr, nullptr, Cv, Cv);
}